// round 1
// baseline (speedup 1.0000x reference)
#include <cuda_runtime.h>
#include <cstddef>

// Problem constants
#define NHEADS   12
#define DHEAD    32
#define NTOK     49          // window tokens (7x7)
#define DIM      384
#define BN_TOTAL 4096        // NUM_WINDOWS * B = 64*64
#define TOKENS   (BN_TOTAL * NTOK)   // 200704
#define QKV_COLS 1152

// Scratch (allocation-free rule: device globals)
__device__ float g_qkv[(size_t)TOKENS * QKV_COLS];   // [t][1152]  (q|k|v interleaved per token)
__device__ float g_ctx[(size_t)TOKENS * DIM];        // [t][384]   attention output (b, n, h*d)

// ---------------------------------------------------------------------------
// SGEMM (NT): C[m][n] = sum_k A[m][k] * B[n][k] + bias[n]
// BM=BN=128, BK=8, 256 threads, 8x8 microtile, double-buffered smem.
// Requires M%128==0, N%128==0, K%8==0 (true for both call sites).
// ---------------------------------------------------------------------------
__global__ __launch_bounds__(256) void sgemm_nt_bias(
    const float* __restrict__ A, const float* __restrict__ B,
    const float* __restrict__ bias, float* __restrict__ C,
    int M, int N, int K)
{
    constexpr int BM = 128, BN = 128, BK = 8, TM = 8, TN = 8;
    __shared__ float As[2][BK][BM];
    __shared__ float Bs[2][BK][BN];

    const int tid = threadIdx.x;
    const int m0 = blockIdx.y * BM;
    const int n0 = blockIdx.x * BN;

    const int lr = tid >> 1;          // 0..127: row within tile
    const int lc = (tid & 1) * 4;     // 0 or 4: k-offset (float4)

    const float* Aptr = A + (size_t)(m0 + lr) * K + lc;
    const float* Bptr = B + (size_t)(n0 + lr) * K + lc;

    float4 a4 = *(const float4*)Aptr;
    float4 b4 = *(const float4*)Bptr;
    As[0][lc + 0][lr] = a4.x; As[0][lc + 1][lr] = a4.y;
    As[0][lc + 2][lr] = a4.z; As[0][lc + 3][lr] = a4.w;
    Bs[0][lc + 0][lr] = b4.x; Bs[0][lc + 1][lr] = b4.y;
    Bs[0][lc + 2][lr] = b4.z; Bs[0][lc + 3][lr] = b4.w;
    __syncthreads();

    const int tx = tid & 15;   // 16 cols of threads
    const int ty = tid >> 4;   // 16 rows of threads

    float acc[TM][TN] = {};
    float ar[TM], br[TN];

    const int nk = K / BK;
    for (int kt = 0; kt < nk; kt++) {
        const int cur = kt & 1;
        const int nxt = cur ^ 1;
        if (kt + 1 < nk) {
            a4 = *(const float4*)(Aptr + (kt + 1) * BK);
            b4 = *(const float4*)(Bptr + (kt + 1) * BK);
        }
        #pragma unroll
        for (int kk = 0; kk < BK; kk++) {
            #pragma unroll
            for (int i = 0; i < TM; i++) ar[i] = As[cur][kk][ty * TM + i];
            #pragma unroll
            for (int j = 0; j < TN; j++) br[j] = Bs[cur][kk][tx * TN + j];
            #pragma unroll
            for (int i = 0; i < TM; i++)
                #pragma unroll
                for (int j = 0; j < TN; j++)
                    acc[i][j] += ar[i] * br[j];
        }
        if (kt + 1 < nk) {
            As[nxt][lc + 0][lr] = a4.x; As[nxt][lc + 1][lr] = a4.y;
            As[nxt][lc + 2][lr] = a4.z; As[nxt][lc + 3][lr] = a4.w;
            Bs[nxt][lc + 0][lr] = b4.x; Bs[nxt][lc + 1][lr] = b4.y;
            Bs[nxt][lc + 2][lr] = b4.z; Bs[nxt][lc + 3][lr] = b4.w;
            __syncthreads();
        }
    }

    // Epilogue: add bias, vectorized stores
    #pragma unroll
    for (int i = 0; i < TM; i++) {
        const int row = m0 + ty * TM + i;
        float* Cp = C + (size_t)row * N + n0 + tx * TN;
        #pragma unroll
        for (int j = 0; j < TN; j += 4) {
            float4 o;
            o.x = acc[i][j + 0] + bias[n0 + tx * TN + j + 0];
            o.y = acc[i][j + 1] + bias[n0 + tx * TN + j + 1];
            o.z = acc[i][j + 2] + bias[n0 + tx * TN + j + 2];
            o.w = acc[i][j + 3] + bias[n0 + tx * TN + j + 3];
            *(float4*)(Cp + j) = o;
        }
    }
}

// ---------------------------------------------------------------------------
// Fused windowed attention: one block per (bn, head).
// scores = (Q K^T)*scale + rel_bias + mask ; softmax ; ctx = P V
// ---------------------------------------------------------------------------
__global__ __launch_bounds__(256) void attn_kernel(
    const float* __restrict__ mask,
    const float* __restrict__ bias_table,
    float* __restrict__ ctx)
{
    __shared__ float sq[NTOK][33];
    __shared__ float sk[NTOK][33];
    __shared__ float sv[NTOK][33];
    __shared__ float ss[NTOK][52];

    const int b  = blockIdx.x;
    const int bn = b / NHEADS;
    const int h  = b - bn * NHEADS;
    const int tid = threadIdx.x;

    const float* base = g_qkv + (size_t)bn * NTOK * QKV_COLS + h * DHEAD;
    for (int e = tid; e < NTOK * DHEAD; e += 256) {
        const int r = e >> 5, c = e & 31;
        const float* p = base + (size_t)r * QKV_COLS + c;
        sq[r][c] = p[0];
        sk[r][c] = p[DIM];
        sv[r][c] = p[2 * DIM];
    }
    __syncthreads();

    const float scale = 0.17677669529663687f;   // 1/sqrt(32)
    const int win = bn >> 6;                    // bn / B, B = 64
    const float* mrow = mask + (size_t)win * (NTOK * NTOK);

    for (int idx = tid; idx < NTOK * NTOK; idx += 256) {
        const int i = idx / NTOK;
        const int j = idx - i * NTOK;
        float acc = 0.f;
        #pragma unroll
        for (int kk = 0; kk < DHEAD; kk++) acc += sq[i][kk] * sk[j][kk];
        const int ih = i / 7, iw = i - ih * 7;
        const int jh = j / 7, jw = j - jh * 7;
        const int ridx = (ih - jh + 6) * 13 + (iw - jw + 6);
        acc = acc * scale + __ldg(&bias_table[ridx * NHEADS + h]) + __ldg(&mrow[idx]);
        ss[i][j] = acc;
    }
    __syncthreads();

    // softmax: one warp per row, 8 warps stride over 49 rows
    const int wid = tid >> 5, lane = tid & 31;
    for (int i = wid; i < NTOK; i += 8) {
        const float v1 = ss[i][lane];
        const float v2 = (lane < 17) ? ss[i][lane + 32] : -1e30f;
        float m = fmaxf(v1, v2);
        #pragma unroll
        for (int o = 16; o > 0; o >>= 1) m = fmaxf(m, __shfl_xor_sync(0xffffffffu, m, o));
        const float e1 = __expf(v1 - m);
        const float e2 = (lane < 17) ? __expf(v2 - m) : 0.f;
        float s = e1 + e2;
        #pragma unroll
        for (int o = 16; o > 0; o >>= 1) s += __shfl_xor_sync(0xffffffffu, s, o);
        const float inv = 1.f / s;
        ss[i][lane] = e1 * inv;
        if (lane < 17) ss[i][lane + 32] = e2 * inv;
    }
    __syncthreads();

    // ctx = P @ V, write [bn][n][h*32 + d] layout (natural for proj GEMM)
    float* obase = ctx + (size_t)bn * NTOK * DIM + h * DHEAD;
    for (int e = tid; e < NTOK * DHEAD; e += 256) {
        const int i = e >> 5, d = e & 31;
        float acc = 0.f;
        #pragma unroll
        for (int j = 0; j < NTOK; j++) acc += ss[i][j] * sv[j][d];
        obase[(size_t)i * DIM + d] = acc;
    }
}

// ---------------------------------------------------------------------------
extern "C" void kernel_launch(void* const* d_in, const int* in_sizes, int n_in,
                              void* d_out, int out_size)
{
    const float* x          = (const float*)d_in[0];
    const float* mask       = (const float*)d_in[1];
    const float* w_qkv      = (const float*)d_in[2];
    const float* b_qkv      = (const float*)d_in[3];
    const float* w_proj     = (const float*)d_in[4];
    const float* b_proj     = (const float*)d_in[5];
    const float* bias_table = (const float*)d_in[6];
    float* out = (float*)d_out;

    float* qkv = nullptr;
    float* ctx = nullptr;
    cudaGetSymbolAddress((void**)&qkv, g_qkv);
    cudaGetSymbolAddress((void**)&ctx, g_ctx);

    // 1) QKV projection: [200704,384] x [1152,384]^T + b_qkv -> g_qkv
    {
        dim3 grid(QKV_COLS / 128, TOKENS / 128);
        sgemm_nt_bias<<<grid, 256>>>(x, w_qkv, b_qkv, qkv, TOKENS, QKV_COLS, DIM);
    }
    // 2) fused windowed attention -> g_ctx
    {
        attn_kernel<<<BN_TOTAL * NHEADS, 256>>>(mask, bias_table, ctx);
    }
    // 3) output projection: [200704,384] x [384,384]^T + b_proj -> out
    {
        dim3 grid(DIM / 128, TOKENS / 128);
        sgemm_nt_bias<<<grid, 256>>>(ctx, w_proj, b_proj, out, TOKENS, DIM, DIM);
    }
}

// round 4
// speedup vs baseline: 1.5403x; 1.5403x over previous
#include <cuda_runtime.h>
#include <cuda_fp16.h>
#include <cstdint>
#include <cstddef>

// ---------------------------------------------------------------------------
// Problem constants
// ---------------------------------------------------------------------------
#define NHEADS   12
#define DHEAD    32
#define NTOK     49
#define DIM      384
#define BN_TOTAL 4096
#define TOKENS   (BN_TOTAL * NTOK)   // 200704
#define QKV_COLS 1152

// Scratch (allocation-free rule: device globals)
__device__ float g_qkv[(size_t)TOKENS * QKV_COLS];
__device__ float g_ctx[(size_t)TOKENS * DIM];

// ---------------------------------------------------------------------------
// fp16-split (3xMMA) GEMM (NT): C[m][n] = sum_k A[m][k]*B[n][k] + bias[n]
// A = A_hi + A_lo (fp16 RN split), likewise B; D += Ah*Bh + Al*Bh + Ah*Bl.
// BM=BN=128, BK=16, double-buffered smem, 256 threads (8 warps, 2x4),
// warp tile 64x32 via m16n8k16 f16 MMA with f32 accumulate.
// Requires M%128==0, N%128==0, K%16==0.
// ---------------------------------------------------------------------------
#define BM 128
#define BN 128
#define BK 16
#define WSTRIDE 12   // uint32 words per row: 8 data (16 halves) + 4 pad (conflict-free)

__device__ __forceinline__ void mma_f16(float* d, const uint32_t* a, const uint32_t* b) {
    asm volatile(
        "mma.sync.aligned.m16n8k16.row.col.f32.f16.f16.f32 "
        "{%0,%1,%2,%3}, {%4,%5,%6,%7}, {%8,%9}, {%0,%1,%2,%3};"
        : "+f"(d[0]), "+f"(d[1]), "+f"(d[2]), "+f"(d[3])
        : "r"(a[0]), "r"(a[1]), "r"(a[2]), "r"(a[3]), "r"(b[0]), "r"(b[1]));
}

__device__ __forceinline__ void split2(float x, float y, uint32_t& hi, uint32_t& lo) {
    half2 h = __floats2half2_rn(x, y);
    float rx = x - __low2float(h);
    float ry = y - __high2float(h);
    half2 l = __floats2half2_rn(rx, ry);
    hi = *(uint32_t*)&h;
    lo = *(uint32_t*)&l;
}

__global__ __launch_bounds__(256)
void gemm_f16split_nt(const float* __restrict__ A, const float* __restrict__ B,
                      const float* __restrict__ bias, float* __restrict__ C,
                      int M, int N, int K)
{
    __shared__ uint32_t AsH[2][BM][WSTRIDE];
    __shared__ uint32_t AsL[2][BM][WSTRIDE];
    __shared__ uint32_t BsH[2][BN][WSTRIDE];
    __shared__ uint32_t BsL[2][BN][WSTRIDE];

    const int tid  = threadIdx.x;
    const int wid  = tid >> 5;
    const int lane = tid & 31;
    const int g = lane >> 2;      // fragment row group
    const int c = lane & 3;       // fragment k word

    const int wm = wid & 1;       // warp row (2)
    const int wn = wid >> 1;      // warp col (4)

    const int m0 = blockIdx.y * BM;
    const int n0 = blockIdx.x * BN;

    const float* Ag = A + (size_t)m0 * K;
    const float* Bg = B + (size_t)n0 * K;

    // staging: thread handles rows (sr, sr+64), float4 quarter sk4 of each 16-float row chunk
    const int sr  = tid >> 2;     // 0..63
    const int sk4 = tid & 3;      // 0..3

    // ---- stage chunk 0 into buffer 0 ----
    #pragma unroll
    for (int p = 0; p < 2; p++) {
        const int row = sr + p * 64;
        float4 va = *(const float4*)(Ag + (size_t)row * K + sk4 * 4);
        float4 vb = *(const float4*)(Bg + (size_t)row * K + sk4 * 4);
        uint32_t h0, l0, h1, l1;
        split2(va.x, va.y, h0, l0); split2(va.z, va.w, h1, l1);
        AsH[0][row][2 * sk4] = h0; AsH[0][row][2 * sk4 + 1] = h1;
        AsL[0][row][2 * sk4] = l0; AsL[0][row][2 * sk4 + 1] = l1;
        split2(vb.x, vb.y, h0, l0); split2(vb.z, vb.w, h1, l1);
        BsH[0][row][2 * sk4] = h0; BsH[0][row][2 * sk4 + 1] = h1;
        BsL[0][row][2 * sk4] = l0; BsL[0][row][2 * sk4 + 1] = l1;
    }
    __syncthreads();

    float acc[4][4][4];
    #pragma unroll
    for (int i = 0; i < 4; i++)
        #pragma unroll
        for (int j = 0; j < 4; j++)
            #pragma unroll
            for (int r = 0; r < 4; r++) acc[i][j][r] = 0.f;

    const int NK = K / BK;       // 24
    float4 ra[2], rb[2];

    for (int kt = 0; kt < NK; kt++) {
        const int cur = kt & 1, nxt = cur ^ 1;

        // prefetch next chunk (global -> regs)
        if (kt + 1 < NK) {
            const int k0 = (kt + 1) * BK;
            #pragma unroll
            for (int p = 0; p < 2; p++) {
                const int row = sr + p * 64;
                ra[p] = *(const float4*)(Ag + (size_t)row * K + k0 + sk4 * 4);
                rb[p] = *(const float4*)(Bg + (size_t)row * K + k0 + sk4 * 4);
            }
        }

        // ---- one k16 MMA step on buffer cur ----
        {
            uint32_t aH[4][4], aL[4][4], bH[4][2], bL[4][2];
            #pragma unroll
            for (int tm = 0; tm < 4; tm++) {
                const int r = wm * 64 + tm * 16 + g;
                aH[tm][0] = AsH[cur][r][c];     aH[tm][1] = AsH[cur][r + 8][c];
                aH[tm][2] = AsH[cur][r][c + 4]; aH[tm][3] = AsH[cur][r + 8][c + 4];
                aL[tm][0] = AsL[cur][r][c];     aL[tm][1] = AsL[cur][r + 8][c];
                aL[tm][2] = AsL[cur][r][c + 4]; aL[tm][3] = AsL[cur][r + 8][c + 4];
            }
            #pragma unroll
            for (int tn = 0; tn < 4; tn++) {
                const int r = wn * 32 + tn * 8 + g;
                bH[tn][0] = BsH[cur][r][c]; bH[tn][1] = BsH[cur][r][c + 4];
                bL[tn][0] = BsL[cur][r][c]; bL[tn][1] = BsL[cur][r][c + 4];
            }
            #pragma unroll
            for (int tm = 0; tm < 4; tm++)
                #pragma unroll
                for (int tn = 0; tn < 4; tn++) {
                    mma_f16(acc[tm][tn], aH[tm], bH[tn]);
                    mma_f16(acc[tm][tn], aL[tm], bH[tn]);
                    mma_f16(acc[tm][tn], aH[tm], bL[tn]);
                }
        }

        // store prefetched regs into buffer nxt (with split)
        if (kt + 1 < NK) {
            #pragma unroll
            for (int p = 0; p < 2; p++) {
                const int row = sr + p * 64;
                uint32_t h0, l0, h1, l1;
                split2(ra[p].x, ra[p].y, h0, l0); split2(ra[p].z, ra[p].w, h1, l1);
                AsH[nxt][row][2 * sk4] = h0; AsH[nxt][row][2 * sk4 + 1] = h1;
                AsL[nxt][row][2 * sk4] = l0; AsL[nxt][row][2 * sk4 + 1] = l1;
                split2(rb[p].x, rb[p].y, h0, l0); split2(rb[p].z, rb[p].w, h1, l1);
                BsH[nxt][row][2 * sk4] = h0; BsH[nxt][row][2 * sk4 + 1] = h1;
                BsL[nxt][row][2 * sk4] = l0; BsL[nxt][row][2 * sk4 + 1] = l1;
            }
        }
        __syncthreads();
    }

    // ---- epilogue: bias + store (float2 per fragment row) ----
    #pragma unroll
    for (int tm = 0; tm < 4; tm++) {
        const int r = m0 + wm * 64 + tm * 16 + g;
        #pragma unroll
        for (int tn = 0; tn < 4; tn++) {
            const int col = n0 + wn * 32 + tn * 8 + 2 * c;
            const float b0 = __ldg(&bias[col]);
            const float b1 = __ldg(&bias[col + 1]);
            float2 o0 = make_float2(acc[tm][tn][0] + b0, acc[tm][tn][1] + b1);
            float2 o1 = make_float2(acc[tm][tn][2] + b0, acc[tm][tn][3] + b1);
            *(float2*)(C + (size_t)r * N + col)       = o0;
            *(float2*)(C + (size_t)(r + 8) * N + col) = o1;
        }
    }
}

// ---------------------------------------------------------------------------
// Fused windowed attention (unchanged from passing baseline)
// ---------------------------------------------------------------------------
__global__ __launch_bounds__(256) void attn_kernel(
    const float* __restrict__ mask,
    const float* __restrict__ bias_table,
    float* __restrict__ ctx)
{
    __shared__ float sq[NTOK][33];
    __shared__ float sk[NTOK][33];
    __shared__ float sv[NTOK][33];
    __shared__ float ss[NTOK][52];

    const int b  = blockIdx.x;
    const int bn = b / NHEADS;
    const int h  = b - bn * NHEADS;
    const int tid = threadIdx.x;

    const float* base = g_qkv + (size_t)bn * NTOK * QKV_COLS + h * DHEAD;
    for (int e = tid; e < NTOK * DHEAD; e += 256) {
        const int r = e >> 5, cc = e & 31;
        const float* p = base + (size_t)r * QKV_COLS + cc;
        sq[r][cc] = p[0];
        sk[r][cc] = p[DIM];
        sv[r][cc] = p[2 * DIM];
    }
    __syncthreads();

    const float scale = 0.17677669529663687f;
    const int win = bn >> 6;
    const float* mrow = mask + (size_t)win * (NTOK * NTOK);

    for (int idx = tid; idx < NTOK * NTOK; idx += 256) {
        const int i = idx / NTOK;
        const int j = idx - i * NTOK;
        float acc = 0.f;
        #pragma unroll
        for (int kk = 0; kk < DHEAD; kk++) acc += sq[i][kk] * sk[j][kk];
        const int ih = i / 7, iw = i - ih * 7;
        const int jh = j / 7, jw = j - jh * 7;
        const int ridx = (ih - jh + 6) * 13 + (iw - jw + 6);
        acc = acc * scale + __ldg(&bias_table[ridx * NHEADS + h]) + __ldg(&mrow[idx]);
        ss[i][j] = acc;
    }
    __syncthreads();

    const int wid = tid >> 5, lane = tid & 31;
    for (int i = wid; i < NTOK; i += 8) {
        const float v1 = ss[i][lane];
        const float v2 = (lane < 17) ? ss[i][lane + 32] : -1e30f;
        float m = fmaxf(v1, v2);
        #pragma unroll
        for (int o = 16; o > 0; o >>= 1) m = fmaxf(m, __shfl_xor_sync(0xffffffffu, m, o));
        const float e1 = __expf(v1 - m);
        const float e2 = (lane < 17) ? __expf(v2 - m) : 0.f;
        float s = e1 + e2;
        #pragma unroll
        for (int o = 16; o > 0; o >>= 1) s += __shfl_xor_sync(0xffffffffu, s, o);
        const float inv = 1.f / s;
        ss[i][lane] = e1 * inv;
        if (lane < 17) ss[i][lane + 32] = e2 * inv;
    }
    __syncthreads();

    float* obase = ctx + (size_t)bn * NTOK * DIM + h * DHEAD;
    for (int e = tid; e < NTOK * DHEAD; e += 256) {
        const int i = e >> 5, d = e & 31;
        float acc = 0.f;
        #pragma unroll
        for (int j = 0; j < NTOK; j++) acc += ss[i][j] * sv[j][d];
        obase[(size_t)i * DIM + d] = acc;
    }
}

// ---------------------------------------------------------------------------
extern "C" void kernel_launch(void* const* d_in, const int* in_sizes, int n_in,
                              void* d_out, int out_size)
{
    const float* x          = (const float*)d_in[0];
    const float* mask       = (const float*)d_in[1];
    const float* w_qkv      = (const float*)d_in[2];
    const float* b_qkv      = (const float*)d_in[3];
    const float* w_proj     = (const float*)d_in[4];
    const float* b_proj     = (const float*)d_in[5];
    const float* bias_table = (const float*)d_in[6];
    float* out = (float*)d_out;

    float* qkv = nullptr;
    float* ctx = nullptr;
    cudaGetSymbolAddress((void**)&qkv, g_qkv);
    cudaGetSymbolAddress((void**)&ctx, g_ctx);

    // 1) QKV projection
    {
        dim3 grid(QKV_COLS / 128, TOKENS / 128);
        gemm_f16split_nt<<<grid, 256>>>(x, w_qkv, b_qkv, qkv, TOKENS, QKV_COLS, DIM);
    }
    // 2) fused windowed attention
    attn_kernel<<<BN_TOTAL * NHEADS, 256>>>(mask, bias_table, ctx);
    // 3) output projection
    {
        dim3 grid(DIM / 128, TOKENS / 128);
        gemm_f16split_nt<<<grid, 256>>>(ctx, w_proj, b_proj, out, TOKENS, DIM, DIM);
    }
}